// round 7
// baseline (speedup 1.0000x reference)
#include <cuda_runtime.h>

#define BDIM 128
#define CH   48                      // matrices per chunk
#define CHF  (CH * 81)               // 3888 floats per chunk
#define SMEM_DYN (2 * CHF * sizeof(float))   // 31104 B double buffer -> 7 blocks/SM

__device__ __forceinline__ void cp_async16(float* sdst, const float* gsrc) {
    unsigned sa = (unsigned)__cvta_generic_to_shared(sdst);
    asm volatile("cp.async.cg.shared.global [%0], [%1], 16;" :: "r"(sa), "l"(gsrc));
}
__device__ __forceinline__ void cp_async4(float* sdst, const float* gsrc) {
    unsigned sa = (unsigned)__cvta_generic_to_shared(sdst);
    asm volatile("cp.async.ca.shared.global [%0], [%1], 4;" :: "r"(sa), "l"(gsrc));
}

__device__ __forceinline__ void issue_load(float* sbuf, const float* __restrict__ X,
                                           int chunk, int B) {
    int bstart = chunk * CH;
    int nm = min(CH, B - bstart);
    int nf = nm * 81;
    const float* g = X + (size_t)bstart * 81;
    int nv4 = nf >> 2;
    for (int i = threadIdx.x; i < nv4; i += BDIM)
        cp_async16(sbuf + 4 * i, g + 4 * i);
    for (int i = (nv4 << 2) + threadIdx.x; i < nf; i += BDIM)
        cp_async4(sbuf + i, g + i);
    asm volatile("cp.async.commit_group;");
}

// divided difference (log a - log b)/(a - b), a >= b > 0, g = a - b.
__device__ __forceinline__ float dd_log(float a, float b, float g) {
    float s = a + b;
    float w = __fdividef(g, s);
    if (w > 0.02f)
        return __fdividef(__logf(__fdividef(a, b)), g);
    return __fdividef(2.0f, s) * fmaf(w * w, 0.33333333f, 1.0f);
}

__global__ __launch_bounds__(BDIM, 7) void spd_kernel(const float* __restrict__ X,
                                                      const float* __restrict__ W1,
                                                      const float* __restrict__ W2,
                                                      const float* __restrict__ W3,
                                                      float* __restrict__ out,
                                                      int B, int nch) {
    extern __shared__ __align__(16) float dsm[];
    float* bufs[2] = { dsm, dsm + CHF };
    __shared__ float sW[27];

    const int tid = threadIdx.x;

    // Wc = W1 @ W2 @ W3 (9x3), computed per block (tiny; L2-resident)
    if (tid < 27) {
        int i = tid / 3, cc = tid % 3;
        float s = 0.f;
        #pragma unroll
        for (int m5 = 0; m5 < 5; ++m5) {
            float t = 0.f;
            #pragma unroll
            for (int k = 0; k < 7; ++k)
                t = fmaf(__ldg(W1 + i * 7 + k), __ldg(W2 + k * 5 + m5), t);
            s = fmaf(t, __ldg(W3 + m5 * 3 + cc), s);
        }
        sW[tid] = s;
    }

    int c = blockIdx.x;
    const int stride = gridDim.x;
    if (c < nch) issue_load(bufs[0], X, c, B);

    int pb = 0;
    for (; c < nch; c += stride, pb ^= 1) {
        int cn = c + stride;
        if (cn < nch) {
            issue_load(bufs[pb ^ 1], X, cn, B);     // prefetch overlaps compute
            asm volatile("cp.async.wait_group 1;");
        } else {
            asm volatile("cp.async.wait_group 0;");
        }
        __syncthreads();   // chunk c data visible (also orders sW on first iter)

        const int bstart = c * CH;
        const int nm = min(CH, B - bstart);

        float2 r01, r23, r45;
        if (tid < nm) {
            const float* m = bufs[pb] + tid * 81;  // stride 81 (odd) -> conflict-free

            // C = Wc^T X Wc, symmetric 3x3
            float c00 = 0.f, c01 = 0.f, c02 = 0.f, c11 = 0.f, c12 = 0.f, c22 = 0.f;
            #pragma unroll
            for (int i = 0; i < 9; ++i) {
                float u0 = 0.f, u1 = 0.f, u2 = 0.f;
                #pragma unroll
                for (int j = 0; j < 9; ++j) {
                    float xv = m[i * 9 + j];
                    u0 = fmaf(xv, sW[j * 3 + 0], u0);
                    u1 = fmaf(xv, sW[j * 3 + 1], u1);
                    u2 = fmaf(xv, sW[j * 3 + 2], u2);
                }
                float w0 = sW[i * 3 + 0], w1 = sW[i * 3 + 1], w2 = sW[i * 3 + 2];
                c00 = fmaf(w0, u0, c00);
                c01 = fmaf(w0, u1, c01);
                c02 = fmaf(w0, u2, c02);
                c11 = fmaf(w1, u1, c11);
                c12 = fmaf(w1, u2, c12);
                c22 = fmaf(w2, u2, c22);
            }

            // ---- 3x3 symmetric eigenvalues (trig closed form, fast math) ----
            float q = (c00 + c11 + c22) * (1.0f / 3.0f);
            float b00 = c00 - q, b11 = c11 - q, b22 = c22 - q;
            float p2 = b00 * b00 + b11 * b11 + b22 * b22 +
                       2.0f * (c01 * c01 + c02 * c02 + c12 * c12);
            float p2s = fmaxf(p2 * (1.0f / 6.0f), 1e-30f);
            float p = p2s * rsqrtf(p2s);            // sqrt(p2s)
            float pinv = __fdividef(1.0f, fmaxf(p, 1e-20f));

            float d00 = b00 * pinv, d11 = b11 * pinv, d22 = b22 * pinv;
            float e01 = c01 * pinv, e02 = c02 * pinv, e12 = c12 * pinv;
            float detB = d00 * (d11 * d22 - e12 * e12)
                       - e01 * (e01 * d22 - e12 * e02)
                       + e02 * (e01 * e12 - d11 * e02);
            float r = 0.5f * detB;
            r = fmaxf(-1.0f, fminf(1.0f, r));
            float phi = acosf(r) * (1.0f / 3.0f);   // [0, pi/3]
            float sph = __sinf(phi);
            float cph = __cosf(phi);
            float l1 = q + 2.0f * p * cph;
            float l3 = q + p * (-cph - 1.7320508075688772f * sph);
            float l2 = 3.0f * q - l1 - l3;

            l3 = fmaxf(l3, 1e-8f);
            l2 = fmaxf(l2, l3);
            l1 = fmaxf(l1, l2);

            // ---- log(A) = d0*I + d1*(A - l3 I) + d2*(A - l3 I)(A - l2 I) ----
            float g32 = l2 - l3, g21 = l1 - l2, g31 = l1 - l3;
            float f32 = dd_log(l2, l3, g32);
            float f21 = dd_log(l1, l2, g21);
            float s31 = l1 + l3;
            float d2v;
            if (g31 > 5e-4f * s31) {
                d2v = __fdividef(f21 - f32, g31);
            } else {
                float h = __fdividef(2.0f, s31);
                d2v = -0.5f * h * h;
            }
            float d0v = __logf(l3);
            float d1v = f32;

            float m00 = c00 - l3, m11 = c11 - l3, m22 = c22 - l3;
            float n00 = c00 - l2, n11 = c11 - l2, n22 = c22 - l2;
            float p00 = m00 * n00 + c01 * c01 + c02 * c02;
            float p01 = m00 * c01 + c01 * n11 + c02 * c12;
            float p02 = m00 * c02 + c01 * c12 + c02 * n22;
            float p11 = c01 * c01 + m11 * n11 + c12 * c12;
            float p12 = c01 * c02 + m11 * c12 + c12 * n22;
            float p22 = c02 * c02 + c12 * c12 + m22 * n22;

            r01.x = fmaf(d2v, p00, fmaf(d1v, m00, d0v));
            r01.y = fmaf(d2v, p01, d1v * c01);
            r23.x = fmaf(d2v, p02, d1v * c02);
            r23.y = fmaf(d2v, p11, fmaf(d1v, m11, d0v));
            r45.x = fmaf(d2v, p12, d1v * c12);
            r45.y = fmaf(d2v, p22, fmaf(d1v, m22, d0v));
        }
        __syncthreads();   // reads of bufs[pb] done before it is refilled next iter

        if (tid < nm) {
            float2* ob = reinterpret_cast<float2*>(out + ((size_t)bstart + tid) * 6);
            ob[0] = r01;
            ob[1] = r23;
            ob[2] = r45;
        }
    }
}

extern "C" void kernel_launch(void* const* d_in, const int* in_sizes, int n_in,
                              void* d_out, int out_size) {
    const float* X  = (const float*)d_in[0];
    const float* W1 = (const float*)d_in[1];
    const float* W2 = (const float*)d_in[2];
    const float* W3 = (const float*)d_in[3];
    float* out = (float*)d_out;

    int B = in_sizes[0] / 81;
    int nch = (B + CH - 1) / CH;

    int sms = 148;
    cudaDeviceGetAttribute(&sms, cudaDevAttrMultiProcessorCount, 0);
    int grid = 7 * sms;              // 7 resident blocks/SM (31.1 KB smem each)
    if (grid > nch) grid = nch;

    spd_kernel<<<grid, BDIM, SMEM_DYN>>>(X, W1, W2, W3, out, B, nch);
}

// round 8
// speedup vs baseline: 1.1231x; 1.1231x over previous
#include <cuda_runtime.h>
#include <cstdint>

#define MC    32                     // matrices per micro-chunk (= warp size)
#define MCF   (MC * 81)              // 2592 floats
#define MCB   (MC * 81 * 4)          // 10368 bytes (16B multiple)
#define SMEM_DYN (2 * MCB)           // 20736 B double buffer per 1-warp block

__device__ __forceinline__ unsigned s2u(const void* p) {
    return (unsigned)__cvta_generic_to_shared(p);
}

__device__ __forceinline__ void mbar_init(unsigned mb, unsigned count) {
    asm volatile("mbarrier.init.shared.b64 [%0], %1;" :: "r"(mb), "r"(count) : "memory");
}
__device__ __forceinline__ void mbar_wait(unsigned mb, unsigned phase) {
    asm volatile(
        "{\n\t"
        ".reg .pred P;\n\t"
        "LW_%=:\n\t"
        "mbarrier.try_wait.parity.acquire.cta.shared::cta.b64 P, [%0], %1, 0x989680;\n\t"
        "@P bra LD_%=;\n\t"
        "bra LW_%=;\n\t"
        "LD_%=:\n\t"
        "}"
        :: "r"(mb), "r"(phase) : "memory");
}

// One bulk async copy: gmem -> smem, completion via mbarrier (lane 0 only).
__device__ __forceinline__ void issue_bulk(unsigned sdst, const float* gsrc,
                                           unsigned bytes, unsigned mb) {
    asm volatile("fence.proxy.async.shared::cta;" ::: "memory");
    asm volatile("mbarrier.arrive.expect_tx.shared.b64 _, [%0], %1;"
                 :: "r"(mb), "r"(bytes) : "memory");
    asm volatile(
        "cp.async.bulk.shared::cta.global.mbarrier::complete_tx::bytes [%0], [%1], %2, [%3];"
        :: "r"(sdst), "l"(gsrc), "r"(bytes), "r"(mb) : "memory");
}

// divided difference (log a - log b)/(a - b), a >= b > 0, g = a - b.
__device__ __forceinline__ float dd_log(float a, float b, float g) {
    float s = a + b;
    float w = __fdividef(g, s);
    if (w > 0.02f)
        return __fdividef(__logf(__fdividef(a, b)), g);
    return __fdividef(2.0f, s) * fmaf(w * w, 0.33333333f, 1.0f);
}

// Full per-matrix pipeline: C = Wc^T X Wc (3x3 sym), then logm(C) vech.
__device__ __forceinline__ void compute_one(const float* __restrict__ m,
                                            const float* __restrict__ sW,
                                            float* __restrict__ outp) {
    float c00 = 0.f, c01 = 0.f, c02 = 0.f, c11 = 0.f, c12 = 0.f, c22 = 0.f;
    #pragma unroll
    for (int i = 0; i < 9; ++i) {
        float u0 = 0.f, u1 = 0.f, u2 = 0.f;
        #pragma unroll
        for (int j = 0; j < 9; ++j) {
            float xv = m[i * 9 + j];
            u0 = fmaf(xv, sW[j * 3 + 0], u0);
            u1 = fmaf(xv, sW[j * 3 + 1], u1);
            u2 = fmaf(xv, sW[j * 3 + 2], u2);
        }
        float w0 = sW[i * 3 + 0], w1 = sW[i * 3 + 1], w2 = sW[i * 3 + 2];
        c00 = fmaf(w0, u0, c00);
        c01 = fmaf(w0, u1, c01);
        c02 = fmaf(w0, u2, c02);
        c11 = fmaf(w1, u1, c11);
        c12 = fmaf(w1, u2, c12);
        c22 = fmaf(w2, u2, c22);
    }

    // 3x3 symmetric eigenvalues (trig closed form, fast math)
    float q = (c00 + c11 + c22) * (1.0f / 3.0f);
    float b00 = c00 - q, b11 = c11 - q, b22 = c22 - q;
    float p2 = b00 * b00 + b11 * b11 + b22 * b22 +
               2.0f * (c01 * c01 + c02 * c02 + c12 * c12);
    float p2s = fmaxf(p2 * (1.0f / 6.0f), 1e-30f);
    float p = p2s * rsqrtf(p2s);            // sqrt
    float pinv = __fdividef(1.0f, fmaxf(p, 1e-20f));

    float d00 = b00 * pinv, d11 = b11 * pinv, d22 = b22 * pinv;
    float e01 = c01 * pinv, e02 = c02 * pinv, e12 = c12 * pinv;
    float detB = d00 * (d11 * d22 - e12 * e12)
               - e01 * (e01 * d22 - e12 * e02)
               + e02 * (e01 * e12 - d11 * e02);
    float r = 0.5f * detB;
    r = fmaxf(-1.0f, fminf(1.0f, r));
    float phi = acosf(r) * (1.0f / 3.0f);   // [0, pi/3]
    float sph = __sinf(phi);
    float cph = __cosf(phi);
    float l1 = q + 2.0f * p * cph;
    float l3 = q + p * (-cph - 1.7320508075688772f * sph);
    float l2 = 3.0f * q - l1 - l3;

    l3 = fmaxf(l3, 1e-8f);
    l2 = fmaxf(l2, l3);
    l1 = fmaxf(l1, l2);

    // log(A) = d0*I + d1*(A - l3 I) + d2*(A - l3 I)(A - l2 I)
    float g32 = l2 - l3, g21 = l1 - l2, g31 = l1 - l3;
    float f32 = dd_log(l2, l3, g32);
    float f21 = dd_log(l1, l2, g21);
    float s31 = l1 + l3;
    float d2v;
    if (g31 > 5e-4f * s31) {
        d2v = __fdividef(f21 - f32, g31);
    } else {
        float h = __fdividef(2.0f, s31);
        d2v = -0.5f * h * h;
    }
    float d0v = __logf(l3);
    float d1v = f32;

    float m00 = c00 - l3, m11 = c11 - l3, m22 = c22 - l3;
    float n00 = c00 - l2, n11 = c11 - l2, n22 = c22 - l2;
    float p00 = m00 * n00 + c01 * c01 + c02 * c02;
    float p01 = m00 * c01 + c01 * n11 + c02 * c12;
    float p02 = m00 * c02 + c01 * c12 + c02 * n22;
    float p11 = c01 * c01 + m11 * n11 + c12 * c12;
    float p12 = c01 * c02 + m11 * c12 + c12 * n22;
    float p22 = c02 * c02 + c12 * c12 + m22 * n22;

    float2 r01, r23, r45;
    r01.x = fmaf(d2v, p00, fmaf(d1v, m00, d0v));
    r01.y = fmaf(d2v, p01, d1v * c01);
    r23.x = fmaf(d2v, p02, d1v * c02);
    r23.y = fmaf(d2v, p11, fmaf(d1v, m11, d0v));
    r45.x = fmaf(d2v, p12, d1v * c12);
    r45.y = fmaf(d2v, p22, fmaf(d1v, m22, d0v));

    float2* ob = reinterpret_cast<float2*>(outp);
    ob[0] = r01;
    ob[1] = r23;
    ob[2] = r45;
}

__global__ __launch_bounds__(32, 10) void spd_kernel(const float* __restrict__ X,
                                                     const float* __restrict__ W1,
                                                     const float* __restrict__ W2,
                                                     const float* __restrict__ W3,
                                                     float* __restrict__ out,
                                                     int B, int nmc) {
    extern __shared__ __align__(16) float dsm[];           // 2 x 2592 floats
    __shared__ __align__(8) unsigned long long mbar_s[2];
    __shared__ float sW[27];

    const int lane = threadIdx.x;

    // Wc = W1 @ W2 @ W3 (9x3); tiny, L2-resident across blocks
    if (lane < 27) {
        int i = lane / 3, cc = lane % 3;
        float s = 0.f;
        #pragma unroll
        for (int m5 = 0; m5 < 5; ++m5) {
            float t = 0.f;
            #pragma unroll
            for (int k = 0; k < 7; ++k)
                t = fmaf(__ldg(W1 + i * 7 + k), __ldg(W2 + k * 5 + m5), t);
            s = fmaf(t, __ldg(W3 + m5 * 3 + cc), s);
        }
        sW[lane] = s;
    }

    unsigned mb0 = s2u(&mbar_s[0]);
    unsigned mb1 = s2u(&mbar_s[1]);
    if (lane == 0) {
        mbar_init(mb0, 1);
        mbar_init(mb1, 1);
    }
    __syncwarp();   // mbarrier init + sW visible warp-wide

    const unsigned mb[2] = { mb0, mb1 };
    unsigned ph[2] = { 0u, 0u };
    const unsigned sbase = s2u(dsm);

    int c = blockIdx.x;
    const int stride = gridDim.x;

    // prologue: load micro-chunk c into buffer 0 (full chunks only)
    if (c < nmc && (c + 1) * MC <= B && lane == 0)
        issue_bulk(sbase, X + (size_t)c * MC * 81, MCB, mb[0]);

    int pb = 0;
    for (; c < nmc; c += stride, pb ^= 1) {
        const int bstart = c * MC;
        const bool full = (bstart + MC <= B);

        // prefetch next micro-chunk into the other buffer
        int cn = c + stride;
        if (cn < nmc && (cn + 1) * MC <= B && lane == 0)
            issue_bulk(sbase + (pb ^ 1) * MCB, X + (size_t)cn * MC * 81, MCB, mb[pb ^ 1]);

        if (full) {
            mbar_wait(mb[pb], ph[pb]);
            ph[pb] ^= 1;
            const float* m = dsm + pb * MCF + lane * 81;  // lane stride 81 -> conflict-free
            compute_one(m, sW, out + ((size_t)bstart + lane) * 6);
        } else {
            // tail micro-chunk: direct gmem reads (rare / absent when B % 32 == 0)
            if (bstart + lane < B) {
                float xl[81];
                const float* g = X + ((size_t)bstart + lane) * 81;
                #pragma unroll
                for (int e = 0; e < 81; ++e) xl[e] = __ldg(g + e);
                compute_one(xl, sW, out + ((size_t)bstart + lane) * 6);
            }
        }
    }
}

extern "C" void kernel_launch(void* const* d_in, const int* in_sizes, int n_in,
                              void* d_out, int out_size) {
    const float* X  = (const float*)d_in[0];
    const float* W1 = (const float*)d_in[1];
    const float* W2 = (const float*)d_in[2];
    const float* W3 = (const float*)d_in[3];
    float* out = (float*)d_out;

    int B = in_sizes[0] / 81;
    int nmc = (B + MC - 1) / MC;

    int sms = 148;
    cudaDeviceGetAttribute(&sms, cudaDevAttrMultiProcessorCount, 0);
    int grid = 10 * sms;             // 10 one-warp blocks/SM (20.7 KB smem each)
    if (grid > nmc) grid = nmc;

    spd_kernel<<<grid, 32, SMEM_DYN>>>(X, W1, W2, W3, out, B, nmc);
}